// round 14
// baseline (speedup 1.0000x reference)
#include <cuda_runtime.h>

#define NROWS 8192
#define DIM   512
#define HID   1024

// Scratch (allocation-free __device__ globals), 16B-aligned.
// RULE 1 (GB300/ATS trap): NEVER pass these as kernel args from host code.
// RULE 2 (build trap): harness lowers via compute_103 PTX — tcgen05/TMEM
// instructions DO NOT COMPILE. mma.sync only.
__device__ __align__(16) float g_part[128 * DIM];
__device__ __align__(16) float g_s[DIM];
__device__ __align__(16) float g_a1[DIM], g_c1[DIM];
__device__ __align__(16) float g_a2[DIM], g_c2[DIM];
// Fragment-ordered operands (VALIDATED R10/R11/R13, fingerprint 9.342721e-05):
// A-frag tile (128m x 32k): idx = ((kstep<<3)+mtile)*128 + l*4 + j
// B-frag tile (128n x 32k): idx = ((kstep<<4)+ntile)*64 + l*2 + j
__device__ __align__(16) float g_x1f[(size_t)NROWS * DIM];   // [mb(64)][kb(16)][4096]
__device__ __align__(16) float g_yf[(size_t)NROWS * HID];    // [mb(64)][kb(32)][4096]
__device__ __align__(16) float g_w1f[(size_t)HID * DIM];     // [nb(8)][kb(16)][4096]
__device__ __align__(16) float g_w2f[(size_t)DIM * HID];     // [nb(4)][kb(32)][4096]

// ---------------- helpers ----------------
__device__ __forceinline__ unsigned tf32r(float x) {
    unsigned r;
    asm("cvt.rna.tf32.f32 %0, %1;" : "=r"(r) : "f"(x));
    return r;
}
__device__ __forceinline__ void mma_tf32(float* d, const unsigned* a, const unsigned* b) {
    asm volatile(
        "mma.sync.aligned.m16n8k8.row.col.f32.tf32.tf32.f32 "
        "{%0,%1,%2,%3}, {%4,%5,%6,%7}, {%8,%9}, {%0,%1,%2,%3};"
        : "+f"(d[0]), "+f"(d[1]), "+f"(d[2]), "+f"(d[3])
        : "r"(a[0]), "r"(a[1]), "r"(a[2]), "r"(a[3]), "r"(b[0]), "r"(b[1]));
}
__device__ __forceinline__ void cp16(unsigned dst, const void* src) {
    asm volatile("cp.async.cg.shared.global [%0], [%1], 16;" :: "r"(dst), "l"(src));
}
#define CP_COMMIT()  asm volatile("cp.async.commit_group;")
#define CP_WAIT1()   asm volatile("cp.async.wait_group 1;" ::: "memory")
#define CP_WAIT0()   asm volatile("cp.async.wait_group 0;" ::: "memory")

// ---------------- stage 1: column partial sums of h ----------------
__global__ void colsum_kernel(const float* __restrict__ h) {
    int d  = threadIdx.x;
    int r0 = blockIdx.x * 64;
    float s = 0.f;
#pragma unroll 8
    for (int r = 0; r < 64; r++)
        s += h[(size_t)(r0 + r) * DIM + d];
    g_part[blockIdx.x * DIM + d] = s;
}

// ---------------- stage 2: s = colsum(h)@vw + N*vb ----------------
__global__ void prep1_kernel(const float* __restrict__ vw,
                             const float* __restrict__ vb) {
    __shared__ float hs[DIM];
    for (int i = threadIdx.x; i < DIM; i += blockDim.x) {
        float s = 0.f;
#pragma unroll 8
        for (int b = 0; b < 128; b++) s += g_part[b * DIM + i];
        hs[i] = s;
    }
    __syncthreads();
    int d = blockIdx.x * blockDim.x + threadIdx.x;
    float s = 0.f;
#pragma unroll 8
    for (int k = 0; k < DIM; k++) s = fmaf(hs[k], vw[k * DIM + d], s);
    g_s[d] = s + 8192.0f * vb[d];
}

// ---------------- stage 3: t = s@ow+ob; fold bn affines ----------------
__global__ void prep2_kernel(const float* __restrict__ ow, const float* __restrict__ ob,
                             const float* __restrict__ g1, const float* __restrict__ b1,
                             const float* __restrict__ m1, const float* __restrict__ v1,
                             const float* __restrict__ g2, const float* __restrict__ b2,
                             const float* __restrict__ m2, const float* __restrict__ v2) {
    __shared__ float ss[DIM];
    for (int i = threadIdx.x; i < DIM; i += blockDim.x) ss[i] = g_s[i];
    __syncthreads();
    int d = blockIdx.x * blockDim.x + threadIdx.x;
    float t = 0.f;
#pragma unroll 8
    for (int k = 0; k < DIM; k++) t = fmaf(ss[k], ow[k * DIM + d], t);
    t += ob[d];
    float A1 = g1[d] * rsqrtf(v1[d] + 1e-5f);
    g_a1[d] = A1;
    g_c1[d] = (t - m1[d]) * A1 + b1[d];
    float A2 = g2[d] * rsqrtf(v2[d] + 1e-5f);
    g_a2[d] = A2;
    g_c2[d] = b2[d] - m2[d] * A2;
}

// ---------------- prep: h -> x1 frag tiles (bn1 affine + tf32) ----------------
__global__ void prep_x1_frag(const float* __restrict__ h) {
    int mb = blockIdx.x >> 4, kb = blockIdx.x & 15;
    int tid = threadIdx.x, l = tid & 31, w = tid >> 5;
    float* tile = g_x1f + ((size_t)blockIdx.x << 12);
#pragma unroll
    for (int si = 0; si < 4; si++) {
        int s = w + si * 8;                  // 0..31 = (kstep<<3)+mtile
        int kstep = s >> 3, mtile = s & 7;
        unsigned vj[4];
#pragma unroll
        for (int j = 0; j < 4; j++) {
            int row = mtile * 16 + ((j & 1) << 3) + (l >> 2);
            int cc  = kstep * 8 + ((j >> 1) << 2) + (l & 3);
            int m = mb * 128 + row, k = kb * 32 + cc;
            vj[j] = tf32r(fmaf(h[(size_t)m * DIM + k], g_a1[k], g_c1[k]));
        }
        uint4 o; o.x = vj[0]; o.y = vj[1]; o.z = vj[2]; o.w = vj[3];
        *(uint4*)(tile + s * 128 + l * 4) = o;
    }
}

// ---------------- prep: both weights -> B frag tiles (merged launch) --------
// blocks 0..127: f1w -> g_w1f (K=512,N=1024); 128..255: f2w -> g_w2f.
__global__ void wfrag_all(const float* __restrict__ w1src,
                          const float* __restrict__ w2src) {
    const float* src;
    float* dstbase;
    int K, N, bid;
    if (blockIdx.x < 128) { src = w1src; dstbase = g_w1f; K = DIM; N = HID; bid = blockIdx.x; }
    else                  { src = w2src; dstbase = g_w2f; K = HID; N = DIM; bid = blockIdx.x - 128; }
    int KB = K >> 5;
    int nb = bid / KB, kb = bid % KB;
    int tid = threadIdx.x, l = tid & 31, w = tid >> 5;
    float* tile = dstbase + ((size_t)bid << 12);
#pragma unroll
    for (int si = 0; si < 8; si++) {
        int s = w + si * 8;                  // 0..63 = (kstep<<4)+ntile
        int kstep = s >> 4, ntile = s & 15;
        unsigned vj[2];
#pragma unroll
        for (int j = 0; j < 2; j++) {
            int n  = nb * 128 + ntile * 8 + (l >> 2);
            int k  = kb * 32 + kstep * 8 + (j << 2) + (l & 3);
            vj[j] = tf32r(src[(size_t)k * N + n]);
        }
        uint2 o; o.x = vj[0]; o.y = vj[1];
        *(uint2*)(tile + s * 64 + l * 2) = o;
    }
}

// =====================================================================
// ffn1: 2-stage cp.async, CTA 128x128, 4 warps (2x2), warp 64x64.
// (VALIDATED R13 verbatim.)
// =====================================================================
#define STAGE_CP(st, kb, Abase, Bbase)                                        \
    {                                                                         \
        unsigned sb = smem_base + (unsigned)(st) * 32768u;                    \
        const float* at = (Abase) + ((size_t)(kb) << 12);                     \
        const float* bt = (Bbase) + ((size_t)(kb) << 12);                     \
        _Pragma("unroll")                                                     \
        for (int i = 0; i < 8; i++) {                                         \
            int ch = tid + i * 128;                                           \
            cp16(sb + ch * 16, at + ch * 4);                                  \
            cp16(sb + 16384u + ch * 16, bt + ch * 4);                         \
        }                                                                     \
    }

#define COMPUTE_ST(st)                                                        \
    {                                                                         \
        const unsigned* As = dsm_u + (unsigned)(st) * 8192u;                  \
        const unsigned* Bs = As + 4096u;                                      \
        _Pragma("unroll")                                                     \
        for (int ks = 0; ks < 4; ks++) {                                      \
            unsigned af[4][4], bf[8][2];                                      \
            _Pragma("unroll")                                                 \
            for (int mt = 0; mt < 4; mt++) {                                  \
                uint4 v = *(const uint4*)&As[((ks << 3) + w_m * 4 + mt) * 128 \
                                             + lane * 4];                     \
                af[mt][0] = v.x; af[mt][1] = v.y;                             \
                af[mt][2] = v.z; af[mt][3] = v.w;                             \
            }                                                                 \
            _Pragma("unroll")                                                 \
            for (int nt = 0; nt < 8; nt++) {                                  \
                uint2 v = *(const uint2*)&Bs[((ks << 4) + w_n * 8 + nt) * 64  \
                                             + lane * 2];                     \
                bf[nt][0] = v.x; bf[nt][1] = v.y;                             \
            }                                                                 \
            _Pragma("unroll")                                                 \
            for (int mt = 0; mt < 4; mt++)                                    \
                _Pragma("unroll")                                             \
                for (int nt = 0; nt < 8; nt++)                                \
                    mma_tf32(acc[mt][nt], af[mt], bf[nt]);                    \
        }                                                                     \
    }

__global__ __launch_bounds__(128) void ffn1_kernel(const float* __restrict__ bias) {
    extern __shared__ unsigned dsm_u[];
    unsigned smem_base = (unsigned)__cvta_generic_to_shared(dsm_u);
    const int tid = threadIdx.x;
    const int lane = tid & 31, wid = tid >> 5;
    const int w_m = wid & 1, w_n = wid >> 1;
    const int g = lane >> 2, tg = lane & 3;
    float acc[4][8][4];
#pragma unroll
    for (int mt = 0; mt < 4; mt++)
#pragma unroll
        for (int nt = 0; nt < 8; nt++)
#pragma unroll
            for (int q = 0; q < 4; q++) acc[mt][nt][q] = 0.f;

    const float* Ab = g_x1f + (((size_t)blockIdx.y * 16) << 12);
    const float* Bb = g_w1f + (((size_t)blockIdx.x * 16) << 12);
    STAGE_CP(0, 0, Ab, Bb); CP_COMMIT();
#pragma unroll 1
    for (int kb = 0; kb < 16; kb++) {
        if (kb + 1 < 16) {
            STAGE_CP((kb + 1) & 1, kb + 1, Ab, Bb); CP_COMMIT();
            CP_WAIT1();
        } else {
            CP_WAIT0();
        }
        __syncthreads();
        COMPUTE_ST(kb & 1);
        __syncthreads();
    }
    const int bn = blockIdx.x * 128;
#pragma unroll
    for (int mt = 0; mt < 4; mt++)
#pragma unroll
        for (int nt = 0; nt < 8; nt++) {
            int col0 = bn + w_n * 64 + nt * 8 + 2 * tg;
            float b0 = bias[col0], b1 = bias[col0 + 1];
#pragma unroll
            for (int q = 0; q < 4; q++) {
                int row = w_m * 64 + mt * 16 + g + ((q >> 1) << 3); // local m
                int col = col0 + (q & 1);                            // global k
                float v = fmaxf(acc[mt][nt][q] + ((q & 1) ? b1 : b0), 0.f);
                int kb = col >> 5, cc = col & 31;
                int kstep = cc >> 3, mtile = row >> 4;
                int l = ((row & 7) << 2) | (cc & 3);
                int j = (((cc >> 2) & 1) << 1) | ((row >> 3) & 1);
                g_yf[(((size_t)blockIdx.y * 32 + kb) << 12) +
                     ((kstep << 3) + mtile) * 128 + l * 4 + j] =
                    __uint_as_float(tf32r(v));
            }
        }
}

// =====================================================================
// ffn2: CTA 128m x 64n, 4 warps (2x2), warp 64x32. Grid (8,64) = 512 CTAs.
// Stage = A 16KB + B 8KB = 24KB; 2 stages = 48KB -> ~4 CTAs/SM.
// B reads the n-half of the 128-wide w2f tiles: per kstep, 8 ntiles = 2KB
// contiguous at tile + kstep*1024 + nhalf*512 floats.
// =====================================================================
__global__ __launch_bounds__(128) void ffn2_kernel(
    const float* __restrict__ h, const float* __restrict__ bias,
    float* __restrict__ out) {
    extern __shared__ unsigned dsm_u[];
    unsigned smem_base = (unsigned)__cvta_generic_to_shared(dsm_u);
    const int tid = threadIdx.x;
    const int lane = tid & 31, wid = tid >> 5;
    const int w_m = wid & 1, w_n = wid >> 1;
    const int g = lane >> 2, tg = lane & 3;
    float acc[4][4][4];
#pragma unroll
    for (int mt = 0; mt < 4; mt++)
#pragma unroll
        for (int nt = 0; nt < 4; nt++)
#pragma unroll
            for (int q = 0; q < 4; q++) acc[mt][nt][q] = 0.f;

    const float* Ab = g_yf  + (((size_t)blockIdx.y * 32) << 12);
    const float* Bb = g_w2f + (((size_t)(blockIdx.x >> 1) * 32) << 12);
    const int nhoff = (blockIdx.x & 1) * 512;      // float offset of n-half per kstep

#define STAGE_CP2(st, kb)                                                     \
    {                                                                         \
        unsigned sb = smem_base + (unsigned)(st) * 24576u;                    \
        const float* at = Ab + ((size_t)(kb) << 12);                          \
        const float* bt = Bb + ((size_t)(kb) << 12);                          \
        _Pragma("unroll")                                                     \
        for (int i = 0; i < 8; i++) {                                         \
            int ch = tid + i * 128;                                           \
            cp16(sb + ch * 16, at + ch * 4);                                  \
        }                                                                     \
        _Pragma("unroll")                                                     \
        for (int i = 0; i < 4; i++) {                                         \
            int ch = tid + i * 128;                                           \
            cp16(sb + 16384u + ch * 16,                                       \
                 bt + (ch >> 7) * 1024 + nhoff + (ch & 127) * 4);             \
        }                                                                     \
    }

#define COMPUTE_ST2(st)                                                       \
    {                                                                         \
        const unsigned* As = dsm_u + (unsigned)(st) * 6144u;                  \
        const unsigned* Bs = As + 4096u;                                      \
        _Pragma("unroll")                                                     \
        for (int ks = 0; ks < 4; ks++) {                                      \
            unsigned af[4][4], bf[4][2];                                      \
            _Pragma("unroll")                                                 \
            for (int mt = 0; mt < 4; mt++) {                                  \
                uint4 v = *(const uint4*)&As[((ks << 3) + w_m * 4 + mt) * 128 \
                                             + lane * 4];                     \
                af[mt][0] = v.x; af[mt][1] = v.y;                             \
                af[mt][2] = v.z; af[mt][3] = v.w;                             \
            }                                                                 \
            _Pragma("unroll")                                                 \
            for (int nt = 0; nt < 4; nt++) {                                  \
                uint2 v = *(const uint2*)&Bs[((ks << 3) + w_n * 4 + nt) * 64  \
                                             + lane * 2];                     \
                bf[nt][0] = v.x; bf[nt][1] = v.y;                             \
            }                                                                 \
            _Pragma("unroll")                                                 \
            for (int mt = 0; mt < 4; mt++)                                    \
                _Pragma("unroll")                                             \
                for (int nt = 0; nt < 4; nt++)                                \
                    mma_tf32(acc[mt][nt], af[mt], bf[nt]);                    \
        }                                                                     \
    }

    STAGE_CP2(0, 0); CP_COMMIT();
#pragma unroll 1
    for (int kb = 0; kb < 32; kb++) {
        if (kb + 1 < 32) {
            STAGE_CP2((kb + 1) & 1, kb + 1); CP_COMMIT();
            CP_WAIT1();
        } else {
            CP_WAIT0();
        }
        __syncthreads();
        COMPUTE_ST2(kb & 1);
        __syncthreads();
    }
    // ---- epilogue: residual (bn1-folded h) + f2b, then bn2 affine ----
    const int bm = blockIdx.y * 128;
    const int bnc = blockIdx.x * 64;
#pragma unroll
    for (int nt = 0; nt < 4; nt++) {
        int col = bnc + w_n * 32 + nt * 8 + 2 * tg;
        float2 fbv = *(const float2*)(bias + col);
        float2 a1v = *(const float2*)(g_a1 + col);
        float2 c1v = *(const float2*)(g_c1 + col);
        float2 a2v = *(const float2*)(g_a2 + col);
        float2 c2v = *(const float2*)(g_c2 + col);
#pragma unroll
        for (int mt = 0; mt < 4; mt++) {
            int r0 = bm + w_m * 64 + mt * 16 + g;
            float2 h0 = *(const float2*)(h + (size_t)r0 * DIM + col);
            float2 h1 = *(const float2*)(h + (size_t)(r0 + 8) * DIM + col);
            float2 o0, o1;
            o0.x = (fmaf(h0.x, a1v.x, c1v.x) + acc[mt][nt][0] + fbv.x) * a2v.x + c2v.x;
            o0.y = (fmaf(h0.y, a1v.y, c1v.y) + acc[mt][nt][1] + fbv.y) * a2v.y + c2v.y;
            o1.x = (fmaf(h1.x, a1v.x, c1v.x) + acc[mt][nt][2] + fbv.x) * a2v.x + c2v.x;
            o1.y = (fmaf(h1.y, a1v.y, c1v.y) + acc[mt][nt][3] + fbv.y) * a2v.y + c2v.y;
            *(float2*)(out + (size_t)r0 * DIM + col) = o0;
            *(float2*)(out + (size_t)(r0 + 8) * DIM + col) = o1;
        }
    }
}

extern "C" void kernel_launch(void* const* d_in, const int* in_sizes, int n_in,
                              void* d_out, int out_size) {
    // metadata order: A,h,qw,qb,kw,kb,vw,vb,ow,ob,f1w,f1b,f2w,f2b,bn1_*,bn2_*
    const float* h   = (const float*)d_in[1];
    const float* vw  = (const float*)d_in[6];
    const float* vb  = (const float*)d_in[7];
    const float* ow  = (const float*)d_in[8];
    const float* ob  = (const float*)d_in[9];
    const float* f1w = (const float*)d_in[10];
    const float* f1b = (const float*)d_in[11];
    const float* f2w = (const float*)d_in[12];
    const float* f2b = (const float*)d_in[13];
    const float* b1g = (const float*)d_in[14];
    const float* b1b = (const float*)d_in[15];
    const float* b1m = (const float*)d_in[16];
    const float* b1v = (const float*)d_in[17];
    const float* b2g = (const float*)d_in[18];
    const float* b2b = (const float*)d_in[19];
    const float* b2m = (const float*)d_in[20];
    const float* b2v = (const float*)d_in[21];
    float* out = (float*)d_out;

    cudaFuncSetAttribute(ffn1_kernel, cudaFuncAttributeMaxDynamicSharedMemorySize, 65536);
    cudaFuncSetAttribute(ffn2_kernel, cudaFuncAttributeMaxDynamicSharedMemorySize, 49152);

    colsum_kernel<<<128, 512>>>(h);                 // launch 1
    prep1_kernel<<<2, 256>>>(vw, vb);               // launch 2
    prep2_kernel<<<2, 256>>>(ow, ob, b1g, b1b, b1m, b1v, b2g, b2b, b2m, b2v); // 3
    prep_x1_frag<<<1024, 256>>>(h);                 // launch 4
    wfrag_all<<<256, 256>>>(f1w, f2w);              // launch 5
    dim3 g1(HID / 128, NROWS / 128);                // (8, 64)
    ffn1_kernel<<<g1, 128, 65536>>>(f1b);           // launch 6  <- ncu -s 5 -c 1
    dim3 g2(DIM / 64, NROWS / 128);                 // (8, 64) = 512 CTAs
    ffn2_kernel<<<g2, 128, 49152>>>(h, f2b, out);   // launch 7
}

// round 15
// speedup vs baseline: 2.5218x; 2.5218x over previous
#include <cuda_runtime.h>

#define NROWS 8192
#define DIM   512
#define HID   1024

// Scratch (allocation-free __device__ globals), 16B-aligned.
// RULE 1 (GB300/ATS trap): NEVER pass these as kernel args from host code.
// RULE 2 (build trap): harness lowers via compute_103 PTX — tcgen05/TMEM
// instructions DO NOT COMPILE. mma.sync only.
__device__ __align__(16) float g_part[128 * DIM];
__device__ __align__(16) float g_s[DIM];
__device__ __align__(16) float g_a1[DIM], g_c1[DIM];
__device__ __align__(16) float g_a2[DIM], g_c2[DIM];
// bf16 fragment-ordered operands (word = bf16x2; semantics VALIDATED in R9):
// A-frag tile (128m x 32k), 2048 words:
//   word = ((kstep<<3)+mtile)*128 + lane*4 + wi,  kstep=cc>>4, mtile=row>>4,
//   lane=((row&7)<<2)|((cc>>1)&3), wi=(((cc>>3)&1)<<1)|((row>>3)&1)
//   content: rows mtile*16+(wi&1)*8+(lane>>2), k = kstep*16+(wi>>1)*8+2(lane&3){,+1}
// B-frag tile (32k x 128n), 2048 words:
//   word = ((kstep<<4)+ntile)*64 + lane*2 + j
//   content: n = ntile*8+(lane>>2), k = kstep*16+j*8+2(lane&3){,+1}
__device__ __align__(16) unsigned g_x1b[(size_t)NROWS * DIM / 2];  // [mb64][kb16][2048]
__device__ __align__(16) unsigned g_yb [(size_t)NROWS * HID / 2];  // [mb64][kb32][2048]
__device__ __align__(16) unsigned g_w1b[(size_t)HID * DIM / 2];    // [nb8][kb16][2048]
__device__ __align__(16) unsigned g_w2b[(size_t)DIM * HID / 2];    // [nb4][kb32][2048]

// ---------------- helpers ----------------
__device__ __forceinline__ unsigned packbf(float lo, float hi) {
    unsigned d;
    asm("cvt.rn.bf16x2.f32 %0, %1, %2;" : "=r"(d) : "f"(hi), "f"(lo));
    return d;
}
__device__ __forceinline__ void mma_bf16(float* d, const unsigned* a, const unsigned* b) {
    asm volatile(
        "mma.sync.aligned.m16n8k16.row.col.f32.bf16.bf16.f32 "
        "{%0,%1,%2,%3}, {%4,%5,%6,%7}, {%8,%9}, {%0,%1,%2,%3};"
        : "+f"(d[0]), "+f"(d[1]), "+f"(d[2]), "+f"(d[3])
        : "r"(a[0]), "r"(a[1]), "r"(a[2]), "r"(a[3]), "r"(b[0]), "r"(b[1]));
}
__device__ __forceinline__ void cp16(unsigned dst, const void* src) {
    asm volatile("cp.async.cg.shared.global [%0], [%1], 16;" :: "r"(dst), "l"(src));
}
#define CP_COMMIT()  asm volatile("cp.async.commit_group;")
#define CP_WAIT1()   asm volatile("cp.async.wait_group 1;" ::: "memory")
#define CP_WAIT0()   asm volatile("cp.async.wait_group 0;" ::: "memory")

// ---------------- stage 1: column partial sums of h ----------------
__global__ void colsum_kernel(const float* __restrict__ h) {
    int d  = threadIdx.x;
    int r0 = blockIdx.x * 64;
    float s = 0.f;
#pragma unroll 8
    for (int r = 0; r < 64; r++)
        s += h[(size_t)(r0 + r) * DIM + d];
    g_part[blockIdx.x * DIM + d] = s;
}

// ---------------- stage 2: s = colsum(h)@vw + N*vb ----------------
__global__ void prep1_kernel(const float* __restrict__ vw,
                             const float* __restrict__ vb) {
    __shared__ float hs[DIM];
    for (int i = threadIdx.x; i < DIM; i += blockDim.x) {
        float s = 0.f;
#pragma unroll 8
        for (int b = 0; b < 128; b++) s += g_part[b * DIM + i];
        hs[i] = s;
    }
    __syncthreads();
    int d = blockIdx.x * blockDim.x + threadIdx.x;
    float s = 0.f;
#pragma unroll 8
    for (int k = 0; k < DIM; k++) s = fmaf(hs[k], vw[k * DIM + d], s);
    g_s[d] = s + 8192.0f * vb[d];
}

// ---------------- stage 3: t = s@ow+ob; fold bn affines ----------------
__global__ void prep2_kernel(const float* __restrict__ ow, const float* __restrict__ ob,
                             const float* __restrict__ g1, const float* __restrict__ b1,
                             const float* __restrict__ m1, const float* __restrict__ v1,
                             const float* __restrict__ g2, const float* __restrict__ b2,
                             const float* __restrict__ m2, const float* __restrict__ v2) {
    __shared__ float ss[DIM];
    for (int i = threadIdx.x; i < DIM; i += blockDim.x) ss[i] = g_s[i];
    __syncthreads();
    int d = blockIdx.x * blockDim.x + threadIdx.x;
    float t = 0.f;
#pragma unroll 8
    for (int k = 0; k < DIM; k++) t = fmaf(ss[k], ow[k * DIM + d], t);
    t += ob[d];
    float A1 = g1[d] * rsqrtf(v1[d] + 1e-5f);
    g_a1[d] = A1;
    g_c1[d] = (t - m1[d]) * A1 + b1[d];
    float A2 = g2[d] * rsqrtf(v2[d] + 1e-5f);
    g_a2[d] = A2;
    g_c2[d] = b2[d] - m2[d] * A2;
}

// -------- prep: h -> x1 bf16 A-frag tiles (bn1 affine + rn-bf16 pack) --------
// grid 1024 = [mb(64)][kb(16)], 256 threads; 512 uint4 slots per tile.
__global__ void prep_x1_bf(const float* __restrict__ h) {
    int mb = blockIdx.x >> 4, kb = blockIdx.x & 15;
    unsigned* tile = g_x1b + ((size_t)blockIdx.x << 11);
    int tid = threadIdx.x;
#pragma unroll
    for (int it = 0; it < 2; it++) {
        int slot = tid + it * 256;            // 0..511 = s(16) x lane(32)
        int s = slot >> 5, lane = slot & 31;
        int kstep = s >> 3, mtile = s & 7;
        int r0 = mb * 128 + mtile * 16 + (lane >> 2);
        int k0 = kb * 32 + kstep * 16 + 2 * (lane & 3);
        float a0 = g_a1[k0], c0 = g_c1[k0], a1v = g_a1[k0 + 1], c1v = g_c1[k0 + 1];
        float a8 = g_a1[k0 + 8], c8 = g_c1[k0 + 8], a9 = g_a1[k0 + 9], c9 = g_c1[k0 + 9];
        const float* hr0 = h + (size_t)r0 * DIM;
        const float* hr8 = h + (size_t)(r0 + 8) * DIM;
        uint4 o;
        o.x = packbf(fmaf(hr0[k0], a0, c0),     fmaf(hr0[k0 + 1], a1v, c1v));
        o.y = packbf(fmaf(hr8[k0], a0, c0),     fmaf(hr8[k0 + 1], a1v, c1v));
        o.z = packbf(fmaf(hr0[k0 + 8], a8, c8), fmaf(hr0[k0 + 9], a9, c9));
        o.w = packbf(fmaf(hr8[k0 + 8], a8, c8), fmaf(hr8[k0 + 9], a9, c9));
        *(uint4*)(tile + slot * 4) = o;
    }
}

// -------- prep: weight [K][N] -> bf16 B-frag tiles [nb][kb] --------
// which=0 -> g_w1b; which=1 -> g_w2b (destination chosen IN DEVICE CODE).
__global__ void wfrag_bf(const float* __restrict__ src, int K, int N, int which) {
    unsigned* dstbase = which ? g_w2b : g_w1b;
    int KB = K >> 5;
    int nb = blockIdx.x / KB, kb = blockIdx.x % KB;
    unsigned* tile = dstbase + ((size_t)blockIdx.x << 11);
    int tid = threadIdx.x;
#pragma unroll
    for (int it = 0; it < 4; it++) {
        int slot = tid + it * 256;            // 0..1023 = s2(32) x lane(32)
        int s2 = slot >> 5, lane = slot & 31;
        int kstep = s2 >> 4, ntile = s2 & 15;
        int n  = nb * 128 + ntile * 8 + (lane >> 2);
        int k0 = kb * 32 + kstep * 16 + 2 * (lane & 3);
        uint2 o;
        o.x = packbf(src[(size_t)k0 * N + n],       src[(size_t)(k0 + 1) * N + n]);
        o.y = packbf(src[(size_t)(k0 + 8) * N + n], src[(size_t)(k0 + 9) * N + n]);
        *(uint2*)(tile + slot * 2) = o;
    }
}

// =====================================================================
// 2-stage cp.async bf16 GEMM (R13 skeleton, halved tiles).
// CTA 128x128, BK=32, 128 threads = 4 warps (2x2), warp tile 64x64.
// Stage = A 8KB + B 8KB = 16KB; 2 stages = 32KB dynamic smem.
// =====================================================================
#define STAGE_CPB(st, kb, Abase, Bbase)                                       \
    {                                                                         \
        unsigned sb = smem_base + (unsigned)(st) * 16384u;                    \
        const unsigned* at = (Abase) + ((size_t)(kb) << 11);                  \
        const unsigned* bt = (Bbase) + ((size_t)(kb) << 11);                  \
        _Pragma("unroll")                                                     \
        for (int i = 0; i < 4; i++) {                                         \
            int ch = tid + i * 128;                                           \
            cp16(sb + ch * 16, at + ch * 4);                                  \
            cp16(sb + 8192u + ch * 16, bt + ch * 4);                          \
        }                                                                     \
    }

#define COMPUTE_STB(st)                                                       \
    {                                                                         \
        const unsigned* As = dsm_u + (unsigned)(st) * 4096u;                  \
        const unsigned* Bs = As + 2048u;                                      \
        _Pragma("unroll")                                                     \
        for (int ks = 0; ks < 2; ks++) {                                      \
            unsigned af[4][4], bf[8][2];                                      \
            _Pragma("unroll")                                                 \
            for (int mt = 0; mt < 4; mt++) {                                  \
                uint4 v = *(const uint4*)&As[((ks << 3) + w_m * 4 + mt) * 128 \
                                             + lane * 4];                     \
                af[mt][0] = v.x; af[mt][1] = v.y;                             \
                af[mt][2] = v.z; af[mt][3] = v.w;                             \
            }                                                                 \
            _Pragma("unroll")                                                 \
            for (int nt = 0; nt < 8; nt++) {                                  \
                uint2 v = *(const uint2*)&Bs[((ks << 4) + w_n * 8 + nt) * 64  \
                                             + lane * 2];                     \
                bf[nt][0] = v.x; bf[nt][1] = v.y;                             \
            }                                                                 \
            _Pragma("unroll")                                                 \
            for (int mt = 0; mt < 4; mt++)                                    \
                _Pragma("unroll")                                             \
                for (int nt = 0; nt < 8; nt++)                                \
                    mma_bf16(acc[mt][nt], af[mt], bf[nt]);                    \
        }                                                                     \
    }

#define GEMM_PREB()                                                           \
    extern __shared__ unsigned dsm_u[];                                       \
    unsigned smem_base = (unsigned)__cvta_generic_to_shared(dsm_u);           \
    const int tid = threadIdx.x;                                              \
    const int lane = tid & 31, wid = tid >> 5;                                \
    const int w_m = wid & 1, w_n = wid >> 1;                                  \
    const int g = lane >> 2, tg = lane & 3;                                   \
    float acc[4][8][4];                                                       \
    _Pragma("unroll")                                                         \
    for (int mt = 0; mt < 4; mt++)                                            \
        _Pragma("unroll")                                                     \
        for (int nt = 0; nt < 8; nt++)                                        \
            _Pragma("unroll")                                                 \
            for (int q = 0; q < 4; q++) acc[mt][nt][q] = 0.f;

#define GEMM_MAINLOOPB(Abase, Bbase, KBT)                                     \
    {                                                                         \
        STAGE_CPB(0, 0, Abase, Bbase); CP_COMMIT();                           \
        _Pragma("unroll 1")                                                   \
        for (int kb = 0; kb < (KBT); kb++) {                                  \
            if (kb + 1 < (KBT)) {                                             \
                STAGE_CPB((kb + 1) & 1, kb + 1, Abase, Bbase); CP_COMMIT();   \
                CP_WAIT1();                                                   \
            } else {                                                          \
                CP_WAIT0();                                                   \
            }                                                                 \
            __syncthreads();                                                  \
            COMPUTE_STB(kb & 1);                                              \
            __syncthreads();                                                  \
        }                                                                     \
    }

// ---------------- FFN GEMM 1: yb = bf16(relu(x1 @ w1 + f1b)) (frag store) ----
__global__ __launch_bounds__(128) void ffn1_kernel(const float* __restrict__ bias) {
    GEMM_PREB();
    const unsigned* Ab = g_x1b + (((size_t)blockIdx.y * 16) << 11);
    const unsigned* Bb = g_w1b + (((size_t)blockIdx.x * 16) << 11);
    GEMM_MAINLOOPB(Ab, Bb, 16);
    const int bn = blockIdx.x * 128;
#pragma unroll
    for (int mt = 0; mt < 4; mt++)
#pragma unroll
        for (int nt = 0; nt < 8; nt++) {
            int col0 = bn + w_n * 64 + nt * 8 + 2 * tg;   // even global k of ffn2
            float b0 = bias[col0], b1 = bias[col0 + 1];
            int kb2 = col0 >> 5, cc = col0 & 31;
            int kstep = cc >> 4;
            int wi_hi = ((cc >> 3) & 1) << 1;
            int lane2 = ((cc >> 1) & 3);                  // tg part of dest lane
#pragma unroll
            for (int qh = 0; qh < 2; qh++) {
                int rowg = w_m * 64 + mt * 16 + g + qh * 8;   // local m (0..127)
                float v0 = fmaxf(acc[mt][nt][qh * 2 + 0] + b0, 0.f);
                float v1 = fmaxf(acc[mt][nt][qh * 2 + 1] + b1, 0.f);
                int mtile = rowg >> 4;
                int wi = wi_hi | ((rowg >> 3) & 1);
                int l2 = ((rowg & 7) << 2) | lane2;
                g_yb[(((size_t)blockIdx.y * 32 + kb2) << 11) +
                     (((kstep << 3) + mtile) << 7) + l2 * 4 + wi] = packbf(v0, v1);
            }
        }
}

// ---------------- FFN GEMM 2 + residual + bn2 (row-major out) ----------------
__global__ __launch_bounds__(128) void ffn2_kernel(
    const float* __restrict__ h, const float* __restrict__ bias,
    float* __restrict__ out) {
    GEMM_PREB();
    const unsigned* Ab = g_yb  + (((size_t)blockIdx.y * 32) << 11);
    const unsigned* Bb = g_w2b + (((size_t)blockIdx.x * 32) << 11);
    GEMM_MAINLOOPB(Ab, Bb, 32);
    const int bm = blockIdx.y * 128;
    const int bn = blockIdx.x * 128;
#pragma unroll
    for (int nt = 0; nt < 8; nt++) {
        int col = bn + w_n * 64 + nt * 8 + 2 * tg;
        float2 fbv = *(const float2*)(bias + col);
        float2 a1v = *(const float2*)(g_a1 + col);
        float2 c1v = *(const float2*)(g_c1 + col);
        float2 a2v = *(const float2*)(g_a2 + col);
        float2 c2v = *(const float2*)(g_c2 + col);
#pragma unroll
        for (int mt = 0; mt < 4; mt++) {
            int r0 = bm + w_m * 64 + mt * 16 + g;
            float2 h0 = *(const float2*)(h + (size_t)r0 * DIM + col);
            float2 h1 = *(const float2*)(h + (size_t)(r0 + 8) * DIM + col);
            float2 o0, o1;
            o0.x = (fmaf(h0.x, a1v.x, c1v.x) + acc[mt][nt][0] + fbv.x) * a2v.x + c2v.x;
            o0.y = (fmaf(h0.y, a1v.y, c1v.y) + acc[mt][nt][1] + fbv.y) * a2v.y + c2v.y;
            o1.x = (fmaf(h1.x, a1v.x, c1v.x) + acc[mt][nt][2] + fbv.x) * a2v.x + c2v.x;
            o1.y = (fmaf(h1.y, a1v.y, c1v.y) + acc[mt][nt][3] + fbv.y) * a2v.y + c2v.y;
            *(float2*)(out + (size_t)r0 * DIM + col) = o0;
            *(float2*)(out + (size_t)(r0 + 8) * DIM + col) = o1;
        }
    }
}

extern "C" void kernel_launch(void* const* d_in, const int* in_sizes, int n_in,
                              void* d_out, int out_size) {
    // metadata order: A,h,qw,qb,kw,kb,vw,vb,ow,ob,f1w,f1b,f2w,f2b,bn1_*,bn2_*
    const float* h   = (const float*)d_in[1];
    const float* vw  = (const float*)d_in[6];
    const float* vb  = (const float*)d_in[7];
    const float* ow  = (const float*)d_in[8];
    const float* ob  = (const float*)d_in[9];
    const float* f1w = (const float*)d_in[10];
    const float* f1b = (const float*)d_in[11];
    const float* f2w = (const float*)d_in[12];
    const float* f2b = (const float*)d_in[13];
    const float* b1g = (const float*)d_in[14];
    const float* b1b = (const float*)d_in[15];
    const float* b1m = (const float*)d_in[16];
    const float* b1v = (const float*)d_in[17];
    const float* b2g = (const float*)d_in[18];
    const float* b2b = (const float*)d_in[19];
    const float* b2m = (const float*)d_in[20];
    const float* b2v = (const float*)d_in[21];
    float* out = (float*)d_out;

    cudaFuncSetAttribute(ffn1_kernel, cudaFuncAttributeMaxDynamicSharedMemorySize, 32768);
    cudaFuncSetAttribute(ffn2_kernel, cudaFuncAttributeMaxDynamicSharedMemorySize, 32768);

    colsum_kernel<<<128, 512>>>(h);
    prep1_kernel<<<2, 256>>>(vw, vb);
    prep2_kernel<<<2, 256>>>(ow, ob, b1g, b1b, b1m, b1v, b2g, b2b, b2m, b2v);
    prep_x1_bf<<<1024, 256>>>(h);
    wfrag_bf<<<128, 256>>>(f1w, DIM, HID, 0);   // -> g_w1b
    wfrag_bf<<<128, 256>>>(f2w, HID, DIM, 1);   // -> g_w2b
    dim3 g1(HID / 128, NROWS / 128);   // (8, 64)
    ffn1_kernel<<<g1, 128, 32768>>>(f1b);
    dim3 g2(DIM / 128, NROWS / 128);   // (4, 64)
    ffn2_kernel<<<g2, 128, 32768>>>(h, f2b, out);
}